// round 1
// baseline (speedup 1.0000x reference)
#include <cuda_runtime.h>
#include <math.h>

#define BATCH 16
#define NPTS  16384
#define BNTOT (BATCH*NPTS)
#define GSTAT 8

// ---------------- scratch (device globals: no allocation allowed) -----------
__device__ float g_y1[(size_t)BATCH*64*NPTS];   // pre-BN conv1 out
__device__ float g_y2[(size_t)BATCH*128*NPTS];  // pre-BN conv2 out
__device__ float g_y3[(size_t)BATCH*32*NPTS];   // pre-BN conv3 out
__device__ float g_y4[(size_t)BATCH*512*NPTS];  // pre-BN conv4 out
__device__ float g_y5[(size_t)BATCH*256*NPTS];  // pre-BN conv5 out
__device__ float g_y6[(size_t)BATCH*128*NPTS];  // pre-BN conv6 out
__device__ float g_psum[512*GSTAT];
__device__ float g_psq [512*GSTAT];
__device__ float g_scale[6][512];               // per-layer BN scale  (g*rstd)
__device__ float g_shift[6][512];               // per-layer BN shift  (be - m*g*rstd)
__device__ float g_v[BATCH*32];                 // softpool vector
__device__ float g_bias4[BATCH*512];            // folded conv4 bias

// ---------------- GEMM: Y[b,co,n] = sum_ci W[co,ci]*act(X[b,ci,n]) + bias ---
// act = identity (inLayer<0) or BN+ReLU using g_scale/g_shift[inLayer].
// Tile: 64 out-channels x 256 points, K-chunk 16, 256 threads, 64 acc/thread.
__global__ void __launch_bounds__(256)
gemm_kernel(const float* __restrict__ W, int wstride,
            const float* __restrict__ bias, int biasPerBatch,
            const float* __restrict__ X, int Ci, int inLayer,
            float* __restrict__ Y, int Co, int outTanh)
{
    __shared__ __align__(16) float As[16][65];   // [k][co] padded: conflict-free
    __shared__ __align__(16) float Xs[16][256];  // [k][n]

    const int t  = threadIdx.x;
    const int tn = t & 15;   // column group 0..15
    const int r  = t >> 4;   // row group    0..15
    const int tilesPerBatch = NPTS / 256;        // 64
    const int b   = blockIdx.y / tilesPerBatch;
    const int n0  = (blockIdx.y % tilesPerBatch) * 256;
    const int co0 = blockIdx.x * 64;

    const float* __restrict__ sc = (inLayer >= 0) ? g_scale[inLayer] : (const float*)0;
    const float* __restrict__ sh = (inLayer >= 0) ? g_shift[inLayer] : (const float*)0;

    float acc[4][16];
#pragma unroll
    for (int j = 0; j < 4; j++)
#pragma unroll
        for (int q = 0; q < 16; q++) acc[j][q] = 0.f;

    for (int k0 = 0; k0 < Ci; k0 += 16) {
        // stage weights: coalesced along ci
#pragma unroll
        for (int i = 0; i < 4; i++) {
            int lin = i*256 + t;
            int k = lin & 15, co = lin >> 4;
            int ci = k0 + k, cog = co0 + co;
            float w = 0.f;
            if (ci < Ci && cog < Co) w = W[(size_t)cog * wstride + ci];
            As[k][co] = w;
        }
        // stage inputs: coalesced along n, BN+ReLU applied on the fly
#pragma unroll
        for (int i = 0; i < 16; i++) {
            int lin = i*256 + t;
            int nl = lin & 255, k = lin >> 8;
            int ci = k0 + k;
            float v = 0.f;
            if (ci < Ci) {
                v = X[((size_t)b * Ci + ci) * NPTS + n0 + nl];
                if (inLayer >= 0) v = fmaxf(fmaf(v, sc[ci], sh[ci]), 0.f);
            }
            Xs[k][nl] = v;
        }
        __syncthreads();

#pragma unroll
        for (int kk = 0; kk < 16; kk++) {
            float a0 = As[kk][r*4 + 0];
            float a1 = As[kk][r*4 + 1];
            float a2 = As[kk][r*4 + 2];
            float a3 = As[kk][r*4 + 3];
#pragma unroll
            for (int g = 0; g < 4; g++) {
                float4 xv = *(const float4*)&Xs[kk][g*64 + tn*4];
                acc[0][g*4+0] = fmaf(a0, xv.x, acc[0][g*4+0]);
                acc[0][g*4+1] = fmaf(a0, xv.y, acc[0][g*4+1]);
                acc[0][g*4+2] = fmaf(a0, xv.z, acc[0][g*4+2]);
                acc[0][g*4+3] = fmaf(a0, xv.w, acc[0][g*4+3]);
                acc[1][g*4+0] = fmaf(a1, xv.x, acc[1][g*4+0]);
                acc[1][g*4+1] = fmaf(a1, xv.y, acc[1][g*4+1]);
                acc[1][g*4+2] = fmaf(a1, xv.z, acc[1][g*4+2]);
                acc[1][g*4+3] = fmaf(a1, xv.w, acc[1][g*4+3]);
                acc[2][g*4+0] = fmaf(a2, xv.x, acc[2][g*4+0]);
                acc[2][g*4+1] = fmaf(a2, xv.y, acc[2][g*4+1]);
                acc[2][g*4+2] = fmaf(a2, xv.z, acc[2][g*4+2]);
                acc[2][g*4+3] = fmaf(a2, xv.w, acc[2][g*4+3]);
                acc[3][g*4+0] = fmaf(a3, xv.x, acc[3][g*4+0]);
                acc[3][g*4+1] = fmaf(a3, xv.y, acc[3][g*4+1]);
                acc[3][g*4+2] = fmaf(a3, xv.z, acc[3][g*4+2]);
                acc[3][g*4+3] = fmaf(a3, xv.w, acc[3][g*4+3]);
            }
        }
        __syncthreads();
    }

    // epilogue
#pragma unroll
    for (int j = 0; j < 4; j++) {
        int cog = co0 + r*4 + j;
        if (cog >= Co) continue;
        float bs = biasPerBatch ? bias[(size_t)b * Co + cog] : bias[cog];
        float* yr = &Y[((size_t)b * Co + cog) * NPTS + n0];
#pragma unroll
        for (int g = 0; g < 4; g++) {
            float4 o;
            o.x = acc[j][g*4+0] + bs;
            o.y = acc[j][g*4+1] + bs;
            o.z = acc[j][g*4+2] + bs;
            o.w = acc[j][g*4+3] + bs;
            if (outTanh) { o.x = tanhf(o.x); o.y = tanhf(o.y); o.z = tanhf(o.z); o.w = tanhf(o.w); }
            *(float4*)&yr[g*64 + tn*4] = o;
        }
    }
}

// ---------------- per-channel sum/sumsq (deterministic fixed tree) ----------
__global__ void __launch_bounds__(256)
stats_kernel(const float* __restrict__ Y, int C)
{
    const int c = blockIdx.x, g = blockIdx.y;
    const int per = BNTOT / GSTAT;      // 32768 points
    const int p0 = g * per;
    float s = 0.f, q = 0.f;
    for (int i = threadIdx.x; i < per; i += 256) {
        int p = p0 + i;
        int b = p / NPTS, n = p - b * NPTS;
        float v = Y[((size_t)b * C + c) * NPTS + n];
        s += v;
        q = fmaf(v, v, q);
    }
    __shared__ float ss[256], sq[256];
    ss[threadIdx.x] = s; sq[threadIdx.x] = q;
    __syncthreads();
    for (int st = 128; st > 0; st >>= 1) {
        if (threadIdx.x < st) {
            ss[threadIdx.x] += ss[threadIdx.x + st];
            sq[threadIdx.x] += sq[threadIdx.x + st];
        }
        __syncthreads();
    }
    if (threadIdx.x == 0) {
        g_psum[c*GSTAT + g] = ss[0];
        g_psq [c*GSTAT + g] = sq[0];
    }
}

__global__ void finalize_kernel(const float* __restrict__ gamma,
                                const float* __restrict__ beta, int C, int layer)
{
    int c = blockIdx.x * blockDim.x + threadIdx.x;
    if (c >= C) return;
    float s = 0.f, q = 0.f;
    for (int g = 0; g < GSTAT; g++) { s += g_psum[c*GSTAT + g]; q += g_psq[c*GSTAT + g]; }
    float m   = s * (1.0f / BNTOT);
    float var = q * (1.0f / BNTOT) - m * m;
    float rstd = rsqrtf(var + 1e-5f);
    float scl  = gamma[c] * rstd;
    g_scale[layer][c] = scl;
    g_shift[layer][c] = fmaf(-m, scl, beta[c]);
}

// ---------------- SoftPool: 16 smallest (stable ties) per (b, key channel) --
// then v[b,k] = b9 + sum_{c,p} w9[c,p] * BN3(y3[b,c,idx[p]])
__global__ void __launch_bounds__(256)
softpool_kernel(const float* __restrict__ w9, const float* __restrict__ b9)
{
    const int b = blockIdx.x >> 5;
    const int k = blockIdx.x & 31;
    const int t = threadIdx.x;

    __shared__ float sVal[256];
    __shared__ int   sIdx[256];
    __shared__ int   selIdx[16];

    const float sc = g_scale[2][k], sh = g_shift[2][k];
    const float* __restrict__ row = &g_y3[((size_t)b * 32 + k) * NPTS];

    float lastV = -3.402823466e38f;
    int   lastI = -1;

    for (int p = 0; p < 16; p++) {
        float bv = 3.402823466e38f;
        int   bi = NPTS;
        for (int n = t; n < NPTS; n += 256) {
            float val = fmaf(row[n], sc, sh);
            bool elig = (val > lastV) || (val == lastV && n > lastI);
            if (elig && (val < bv || (val == bv && n < bi))) { bv = val; bi = n; }
        }
        sVal[t] = bv; sIdx[t] = bi;
        __syncthreads();
        for (int st = 128; st > 0; st >>= 1) {
            if (t < st) {
                float ov = sVal[t + st]; int oi = sIdx[t + st];
                if (ov < sVal[t] || (ov == sVal[t] && oi < sIdx[t])) { sVal[t] = ov; sIdx[t] = oi; }
            }
            __syncthreads();
        }
        lastV = sVal[0]; lastI = sIdx[0];
        if (t == 0) selIdx[p] = sIdx[0];
        __syncthreads();
    }

    // v[b,k]
    float part = 0.f;
    for (int i = t; i < 512; i += 256) {   // 32 channels x 16 positions
        int c = i >> 4, p = i & 15;
        int n = selIdx[p];
        float val = fmaf(g_y3[((size_t)b * 32 + c) * NPTS + n], g_scale[2][c], g_shift[2][c]);
        part = fmaf(w9[c * 16 + p], val, part);
    }
    sVal[t] = part;
    __syncthreads();
    for (int st = 128; st > 0; st >>= 1) {
        if (t < st) sVal[t] += sVal[t + st];
        __syncthreads();
    }
    if (t == 0) g_v[b * 32 + k] = sVal[0] + b9[0];
}

// ---------------- fold glob into conv4 bias: bias4[b,co]=b4[co]+sum_k w4[co,k]*v[b,k]
__global__ void bias4_kernel(const float* __restrict__ w4, const float* __restrict__ b4)
{
    int idx = blockIdx.x * 256 + threadIdx.x;   // 16*512
    if (idx >= BATCH * 512) return;
    int b = idx >> 9, co = idx & 511;
    float s = b4[co];
#pragma unroll
    for (int k = 0; k < 32; k++) s = fmaf(w4[co * 96 + k], g_v[b * 32 + k], s);
    g_bias4[idx] = s;
}

// ---------------------------------------------------------------------------
extern "C" void kernel_launch(void* const* d_in, const int* in_sizes, int n_in,
                              void* d_out, int out_size)
{
    const float* x   = (const float*)d_in[0];
    const float* w1  = (const float*)d_in[1];  const float* b1  = (const float*)d_in[2];
    const float* g1  = (const float*)d_in[3];  const float* be1 = (const float*)d_in[4];
    const float* w2  = (const float*)d_in[5];  const float* b2  = (const float*)d_in[6];
    const float* g2  = (const float*)d_in[7];  const float* be2 = (const float*)d_in[8];
    const float* w3  = (const float*)d_in[9];  const float* b3  = (const float*)d_in[10];
    const float* g3  = (const float*)d_in[11]; const float* be3 = (const float*)d_in[12];
    const float* w9  = (const float*)d_in[13]; const float* b9  = (const float*)d_in[14];
    const float* w4  = (const float*)d_in[15]; const float* b4  = (const float*)d_in[16];
    const float* g4  = (const float*)d_in[17]; const float* be4 = (const float*)d_in[18];
    const float* w5  = (const float*)d_in[19]; const float* b5  = (const float*)d_in[20];
    const float* g5  = (const float*)d_in[21]; const float* be5 = (const float*)d_in[22];
    const float* w6  = (const float*)d_in[23]; const float* b6  = (const float*)d_in[24];
    const float* g6  = (const float*)d_in[25]; const float* be6 = (const float*)d_in[26];
    const float* w7  = (const float*)d_in[27]; const float* b7  = (const float*)d_in[28];

    float *y1, *y2, *y3, *y4, *y5, *y6, *bias4p;
    cudaGetSymbolAddress((void**)&y1, g_y1);
    cudaGetSymbolAddress((void**)&y2, g_y2);
    cudaGetSymbolAddress((void**)&y3, g_y3);
    cudaGetSymbolAddress((void**)&y4, g_y4);
    cudaGetSymbolAddress((void**)&y5, g_y5);
    cudaGetSymbolAddress((void**)&y6, g_y6);
    cudaGetSymbolAddress((void**)&bias4p, g_bias4);

    const dim3 blk(256);
    const int NT = BNTOT / 256;   // 1024 column tiles

    // L1: 4 -> 64 (raw input)
    gemm_kernel<<<dim3(1, NT), blk>>>(w1, 4, b1, 0, x, 4, -1, y1, 64, 0);
    stats_kernel<<<dim3(64, GSTAT), blk>>>(y1, 64);
    finalize_kernel<<<1, 256>>>(g1, be1, 64, 0);

    // L2: 64 -> 128
    gemm_kernel<<<dim3(2, NT), blk>>>(w2, 64, b2, 0, y1, 64, 0, y2, 128, 0);
    stats_kernel<<<dim3(128, GSTAT), blk>>>(y2, 128);
    finalize_kernel<<<1, 256>>>(g2, be2, 128, 1);

    // L3: 128 -> 32 (BN only, consumed by softpool)
    gemm_kernel<<<dim3(1, NT), blk>>>(w3, 128, b3, 0, y2, 128, 1, y3, 32, 0);
    stats_kernel<<<dim3(32, GSTAT), blk>>>(y3, 32);
    finalize_kernel<<<1, 256>>>(g3, be3, 32, 2);

    // SoftPool + fold glob into conv4 bias
    softpool_kernel<<<512, 256>>>(w9, b9);
    bias4_kernel<<<32, 256>>>(w4, b4);

    // L4: effectively 64 -> 512 on h1, per-batch bias (glob folded), weight rows offset by 32
    gemm_kernel<<<dim3(8, NT), blk>>>(w4 + 32, 96, bias4p, 1, y1, 64, 0, y4, 512, 0);
    stats_kernel<<<dim3(512, GSTAT), blk>>>(y4, 512);
    finalize_kernel<<<2, 256>>>(g4, be4, 512, 3);

    // L5: 512 -> 256
    gemm_kernel<<<dim3(4, NT), blk>>>(w5, 512, b5, 0, y4, 512, 3, y5, 256, 0);
    stats_kernel<<<dim3(256, GSTAT), blk>>>(y5, 256);
    finalize_kernel<<<1, 256>>>(g5, be5, 256, 4);

    // L6: 256 -> 128
    gemm_kernel<<<dim3(2, NT), blk>>>(w6, 256, b6, 0, y5, 256, 4, y6, 128, 0);
    stats_kernel<<<dim3(128, GSTAT), blk>>>(y6, 128);
    finalize_kernel<<<1, 256>>>(g6, be6, 128, 5);

    // L7: 128 -> 3, tanh, straight to output
    gemm_kernel<<<dim3(1, NT), blk>>>(w7, 128, b7, 0, y6, 128, 5, (float*)d_out, 3, 1);
}